// round 17
// baseline (speedup 1.0000x reference)
#include <cuda_runtime.h>
#include <cuda_bf16.h>
#include <cstdint>

// ContrastiveLoss: fused bf16-split HMMA GEMM + online softmax.
// loss = -(1/B^2) * sum_j w_j * S_j
//   S_j = sum_k l[j,k] - B*max_j - B*log(sum_k exp(l[j,k]-max_j)+eps)
//   l = u @ A^T, u[j] = A[j]/T + (A[j] @ Cov[label_j]) / (2 T^3)
// R13: combine fused into gemm tail (ticket); S_j via colsum dot (exact,
//      out of the gemm); epilogue in log2 domain (ex2.approx) + tile skip.

#define BN 4096
#define DD 128
#define CN 100
#define NSPLIT 4
#define CTILES ((BN / NSPLIT) / 128)   // 8
#define LOG2E 1.4426950408889634
#define LN2   0.6931471805599453

__device__ __align__(16) __nv_bfloat16 g_uhi[BN * DD];
__device__ __align__(16) __nv_bfloat16 g_ulo[BN * DD];
__device__ __align__(16) __nv_bfloat16 g_ahi[BN * DD];
__device__ __align__(16) __nv_bfloat16 g_alo[BN * DD];
__device__ float  g_pmax[NSPLIT * BN];   // log2-domain
__device__ float  g_pse[NSPLIT * BN];
__device__ double g_S[BN];               // exact sum of logits per row
__device__ float  g_csp[8 * DD];         // colsum partials (deterministic)
__device__ int    g_cnt[CN];
__device__ int    g_coff[CN];
__device__ int    g_order[BN];
__device__ int    g_is64;
__device__ double g_acc;
__device__ int    g_tix[BN / 128];       // per-row-block arrival tickets
__device__ int    g_tix2;                // combiner completion ticket

// ---------------------------------------------------------------- helpers
__device__ __forceinline__ uint32_t smem_u32(const void* p) {
    uint32_t a;
    asm("{ .reg .u64 t; cvta.to.shared.u64 t, %1; cvt.u32.u64 %0, t; }"
        : "=r"(a) : "l"(p));
    return a;
}
__device__ __forceinline__ void ldmx4(uint32_t* r, uint32_t addr) {
    asm volatile("ldmatrix.sync.aligned.m8n8.x4.shared.b16 {%0,%1,%2,%3}, [%4];"
                 : "=r"(r[0]), "=r"(r[1]), "=r"(r[2]), "=r"(r[3]) : "r"(addr));
}
__device__ __forceinline__ void mma_bf16(float* c, const uint32_t* a,
                                         uint32_t b0, uint32_t b1) {
    asm volatile(
        "mma.sync.aligned.m16n8k16.row.col.f32.bf16.bf16.f32 "
        "{%0,%1,%2,%3}, {%4,%5,%6,%7}, {%8,%9}, {%0,%1,%2,%3};"
        : "+f"(c[0]), "+f"(c[1]), "+f"(c[2]), "+f"(c[3])
        : "r"(a[0]), "r"(a[1]), "r"(a[2]), "r"(a[3]), "r"(b0), "r"(b1));
}
__device__ __forceinline__ float ex2(float x) {
    float r;
    asm("ex2.approx.ftz.f32 %0, %1;" : "=f"(r) : "f"(x));
    return r;
}
#define CP16(dst, src) asm volatile( \
    "cp.async.ca.shared.global [%0], [%1], 16;" :: "r"(dst), "l"(src))
#define CP_COMMIT() asm volatile("cp.async.commit_group;" ::: "memory")
#define CP_WAIT0()  asm volatile("cp.async.wait_group 0;" ::: "memory")

__device__ __forceinline__ uint32_t pk2(float a, float b) {
    __nv_bfloat162 t = __floats2bfloat162_rn(a, b);
    return *(uint32_t*)&t;
}
__device__ __forceinline__ int lab(const void* L, int t, int is64) {
    int v;
    if (is64) v = (int)((const long long*)L)[t];
    else      v = ((const int*)L)[t];
    return min(max(v, 0), CN - 1);
}

// ---------------------------------------------------------------------------
// Preprocessing. Grid = 9. Block 0: dtype detect, histogram, scan, scatter,
// resets. Blocks 1..8: column-sum partials over 512 rows each (deterministic).
__global__ __launch_bounds__(1024)
void k_pre(const void* __restrict__ labels, const float* __restrict__ A) {
    const int t = threadIdx.x;
    if (blockIdx.x > 0) {
        __shared__ float ps[8][DD];
        const int b = blockIdx.x - 1;
        const int c = t & 127;
        const int rg = t >> 7;
        float s = 0.f;
        for (int r = b * 512 + rg; r < (b + 1) * 512; r += 8)
            s += A[(size_t)r * DD + c];
        ps[rg][c] = s;
        __syncthreads();
        if (rg == 0) {
            float v = 0.f;
#pragma unroll
            for (int p = 0; p < 8; p++) v += ps[p][c];
            g_csp[b * DD + c] = v;
        }
        return;
    }

    __shared__ int hist[128];
    __shared__ int incl[128];
    __shared__ int fill[128];
    __shared__ int is64_s;

    if (t == 0) { is64_s = 1; g_acc = 0.0; g_tix2 = 0; }
    if (t < 128) { hist[t] = 0; fill[t] = 0; }
    if (t < BN / 128) g_tix[t] = 0;
    __syncthreads();
    if (t < 64 && (t & 1) && ((const int*)labels)[t] != 0)
        atomicExch(&is64_s, 0);
    __syncthreads();
    const int is64 = is64_s;
    if (t == 0) g_is64 = is64;

    for (int i = t; i < BN; i += 1024)
        atomicAdd(&hist[lab(labels, i, is64)], 1);
    __syncthreads();

    if (t < 128) incl[t] = hist[t];
    __syncthreads();
#pragma unroll
    for (int off = 1; off < 128; off <<= 1) {
        int v = (t < 128 && t >= off) ? incl[t - off] : 0;
        __syncthreads();
        if (t < 128) incl[t] += v;
        __syncthreads();
    }
    if (t < CN) {
        g_cnt[t] = hist[t];
        g_coff[t] = incl[t] - hist[t];
    }
    __syncthreads();

    for (int i = t; i < BN; i += 1024) {
        int c = lab(labels, i, is64);
        int pos = atomicAdd(&fill[c], 1);
        g_order[(incl[c] - hist[c]) + pos] = i;
    }
}

// ---------------------------------------------------------------------------
// Class-grouped u computation + A hi/lo split + exact S_j = u . colsum.
// u is scaled by LOG2E before the bf16 split (GEMM works in log2 domain).
#define U_SMEM (DD * DD * 4 + 16 * DD * 4 + DD * 4 + 64)

__global__ __launch_bounds__(256)
void k_u_grouped(const float* __restrict__ A, const float* __restrict__ Cov) {
    extern __shared__ char dsm[];
    float* covS  = (float*)dsm;
    float* As    = covS + DD * DD;
    float* csumS = As + 16 * DD;
    int*   rows  = (int*)(csumS + DD);
    const int tid = threadIdx.x;
    const int c = blockIdx.x;
    const int cnt = g_cnt[c];
    if (cnt == 0) return;
    const int base = g_coff[c];

    const float4* Cg = (const float4*)(Cov + (size_t)c * DD * DD);
#pragma unroll
    for (int i = tid; i < DD * DD / 4; i += 256)
        ((float4*)covS)[i] = Cg[i];
    if (tid < DD) {
        float v = 0.f;
#pragma unroll
        for (int p = 0; p < 8; p++) v += g_csp[p * DD + tid];
        csumS[tid] = v;
    }

    const int rg = tid >> 5;
    const int e4 = (tid & 31) * 4;
    const int lid = tid & 31;
    const float invT = (float)(1.0 / 0.07);
    const float s2   = (float)(1.0 / (2.0 * 0.07 * 0.07 * 0.07));

    for (int chunk = 0; chunk < cnt; chunk += 16) {
        __syncthreads();
        if (tid < 16)
            rows[tid] = (chunk + tid < cnt) ? g_order[base + chunk + tid] : -1;
        __syncthreads();

#pragma unroll
        for (int i = tid; i < 512; i += 256) {
            int r = i >> 5, cq = i & 31;
            int row = rows[r];
            float4 v = make_float4(0.f, 0.f, 0.f, 0.f);
            if (row >= 0) v = ((const float4*)(A + (size_t)row * DD))[cq];
            ((float4*)&As[r * DD])[cq] = v;
            if (row >= 0) {
                __nv_bfloat16 h0 = __float2bfloat16(v.x);
                __nv_bfloat16 h1 = __float2bfloat16(v.y);
                __nv_bfloat16 h2 = __float2bfloat16(v.z);
                __nv_bfloat16 h3 = __float2bfloat16(v.w);
                uint2 hi, lo;
                hi.x = pk2(v.x, v.y); hi.y = pk2(v.z, v.w);
                lo.x = pk2(v.x - __bfloat162float(h0), v.y - __bfloat162float(h1));
                lo.y = pk2(v.z - __bfloat162float(h2), v.w - __bfloat162float(h3));
                *(uint2*)(g_ahi + (size_t)row * DD + cq * 4) = hi;
                *(uint2*)(g_alo + (size_t)row * DD + cq * 4) = lo;
            }
        }
        __syncthreads();

        float acc[2][4];
#pragma unroll
        for (int r = 0; r < 2; r++)
#pragma unroll
            for (int q = 0; q < 4; q++) acc[r][q] = 0.f;

#pragma unroll 4
        for (int d = 0; d < DD; d++) {
            float4 cv = *(const float4*)(covS + d * DD + e4);
            float a0 = As[rg * DD + d];
            float a1 = As[(rg + 8) * DD + d];
            acc[0][0] = fmaf(a0, cv.x, acc[0][0]);
            acc[0][1] = fmaf(a0, cv.y, acc[0][1]);
            acc[0][2] = fmaf(a0, cv.z, acc[0][2]);
            acc[0][3] = fmaf(a0, cv.w, acc[0][3]);
            acc[1][0] = fmaf(a1, cv.x, acc[1][0]);
            acc[1][1] = fmaf(a1, cv.y, acc[1][1]);
            acc[1][2] = fmaf(a1, cv.z, acc[1][2]);
            acc[1][3] = fmaf(a1, cv.w, acc[1][3]);
        }

#pragma unroll
        for (int r = 0; r < 2; r++) {
            int row = rows[rg + r * 8];
            if (row < 0) continue;
            float uv[4];
#pragma unroll
            for (int q = 0; q < 4; q++)
                uv[q] = As[(rg + r * 8) * DD + e4 + q] * invT + acc[r][q] * s2;

            // exact S_j partial: dot with colsum (true-logit domain)
            float sp = uv[0] * csumS[e4] + uv[1] * csumS[e4 + 1]
                     + uv[2] * csumS[e4 + 2] + uv[3] * csumS[e4 + 3];
            double sd = (double)sp;
#pragma unroll
            for (int o = 16; o >= 1; o >>= 1)
                sd += __shfl_xor_sync(0xffffffffu, sd, o);
            if (lid == 0) g_S[row] = sd;

            // scale to log2 domain, then bf16 hi/lo split
            float us[4];
#pragma unroll
            for (int q = 0; q < 4; q++) us[q] = uv[q] * (float)LOG2E;
            __nv_bfloat16 h0 = __float2bfloat16(us[0]);
            __nv_bfloat16 h1 = __float2bfloat16(us[1]);
            __nv_bfloat16 h2 = __float2bfloat16(us[2]);
            __nv_bfloat16 h3 = __float2bfloat16(us[3]);
            uint2 hi, lo;
            hi.x = pk2(us[0], us[1]); hi.y = pk2(us[2], us[3]);
            lo.x = pk2(us[0] - __bfloat162float(h0), us[1] - __bfloat162float(h1));
            lo.y = pk2(us[2] - __bfloat162float(h2), us[3] - __bfloat162float(h3));
            *(uint2*)(g_uhi + (size_t)row * DD + e4) = hi;
            *(uint2*)(g_ulo + (size_t)row * DD + e4) = lo;
        }
    }
}

// ---------------------------------------------------------------------------
// Fused HMMA GEMM + per-lane online softmax (log2 domain) + fused combine.
#define SROW 272
#define TILE_B (128 * SROW)
#define OFF_UHI 0
#define OFF_ULO (TILE_B)
#define OFF_A   (2 * TILE_B)
#define SMEM_BYTES (6 * TILE_B)

__global__ __launch_bounds__(256, 1)
void k_gemm_mma(const void* __restrict__ labels, float* __restrict__ out) {
    extern __shared__ char smem[];
    __shared__ int do_combine;
    __shared__ double redC[8];
    const uint32_t sb = smem_u32(smem);
    const int tid = threadIdx.x;
    const int wid = tid >> 5;
    const int lid = tid & 31;
    const int warp_m = wid & 3;
    const int warp_n = wid >> 2;
    const int row0 = blockIdx.x * 128;
    const int colbase = blockIdx.y * (BN / NSPLIT);

    const int rsel = (lid & 7) + ((lid >> 3) & 1) * 8;
    const int csel = ((lid >> 4) & 1) * 16;
    uint32_t aoff[2], boff[4];
#pragma unroll
    for (int mf = 0; mf < 2; mf++)
        aoff[mf] = (uint32_t)((warp_m * 32 + mf * 16 + rsel) * SROW + csel);
#pragma unroll
    for (int q = 0; q < 4; q++)
        boff[q] = (uint32_t)((warp_n * 64 + q * 16 + rsel) * SROW + csel);

#pragma unroll
    for (int i = 0; i < 8; i++) {
        int idx = i * 256 + tid;
        int r = idx >> 4, cq = idx & 15;
        char* dh = smem + OFF_UHI + r * SROW + cq * 16;
        char* dl = smem + OFF_ULO + r * SROW + cq * 16;
        *(uint4*)dh = *((const uint4*)(g_uhi + (size_t)(row0 + r) * DD) + cq);
        *(uint4*)dl = *((const uint4*)(g_ulo + (size_t)(row0 + r) * DD) + cq);
    }
#pragma unroll
    for (int i = 0; i < 8; i++) {
        int idx = i * 256 + tid;
        int r = idx >> 4, cq = idx & 15;
        uint32_t dh = sb + OFF_A + r * SROW + cq * 16;
        CP16(dh, (const char*)(g_ahi + (size_t)(colbase + r) * DD) + cq * 16);
        CP16(dh + TILE_B, (const char*)(g_alo + (size_t)(colbase + r) * DD) + cq * 16);
    }
    CP_COMMIT();
    CP_WAIT0();
    __syncthreads();

    float M[4], L[4];
#pragma unroll
    for (int i = 0; i < 4; i++) { M[i] = -3.0e38f; L[i] = 0.f; }

    for (int ct = 0; ct < CTILES; ct++) {
        const uint32_t ab = sb + OFF_A + (uint32_t)(ct & 1) * (2 * TILE_B);

        if (ct + 1 < CTILES) {
            const int coln = colbase + (ct + 1) * 128;
            const uint32_t nb = sb + OFF_A + (uint32_t)((ct + 1) & 1) * (2 * TILE_B);
#pragma unroll
            for (int i = 0; i < 8; i++) {
                int idx = i * 256 + tid;
                int r = idx >> 4, cq = idx & 15;
                uint32_t dh = nb + r * SROW + cq * 16;
                CP16(dh, (const char*)(g_ahi + (size_t)(coln + r) * DD) + cq * 16);
                CP16(dh + TILE_B,
                     (const char*)(g_alo + (size_t)(coln + r) * DD) + cq * 16);
            }
        }
        CP_COMMIT();

        float acc[2][8][4];
#pragma unroll
        for (int mf = 0; mf < 2; mf++)
#pragma unroll
            for (int nf = 0; nf < 8; nf++)
#pragma unroll
                for (int c = 0; c < 4; c++) acc[mf][nf][c] = 0.f;

#pragma unroll
        for (int ks = 0; ks < 8; ks++) {
            const uint32_t kb = ks * 32;
            uint32_t uh[2][4], ul[2][4], bh[4][4], bl[4][4];
#pragma unroll
            for (int mf = 0; mf < 2; mf++) {
                ldmx4(uh[mf], sb + OFF_UHI + aoff[mf] + kb);
                ldmx4(ul[mf], sb + OFF_ULO + aoff[mf] + kb);
            }
#pragma unroll
            for (int q = 0; q < 4; q++) {
                ldmx4(bh[q], ab + boff[q] + kb);
                ldmx4(bl[q], ab + TILE_B + boff[q] + kb);
            }
#pragma unroll
            for (int mf = 0; mf < 2; mf++)
#pragma unroll
                for (int q = 0; q < 4; q++) {
                    mma_bf16(acc[mf][2 * q],     uh[mf], bh[q][0], bh[q][2]);
                    mma_bf16(acc[mf][2 * q + 1], uh[mf], bh[q][1], bh[q][3]);
                    mma_bf16(acc[mf][2 * q],     uh[mf], bl[q][0], bl[q][2]);
                    mma_bf16(acc[mf][2 * q + 1], uh[mf], bl[q][1], bl[q][3]);
                    mma_bf16(acc[mf][2 * q],     ul[mf], bh[q][0], bh[q][2]);
                    mma_bf16(acc[mf][2 * q + 1], ul[mf], bh[q][1], bh[q][3]);
                }
        }

#pragma unroll
        for (int ri = 0; ri < 4; ri++) {
            const int mf = ri >> 1, rp = ri & 1;
            float vmax = -3.0e38f;
#pragma unroll
            for (int nf = 0; nf < 8; nf++) {
                vmax = fmaxf(vmax, acc[mf][nf][rp * 2]);
                vmax = fmaxf(vmax, acc[mf][nf][rp * 2 + 1]);
            }
            // whole-warp skip: tile provably irrelevant (< M - 32 in log2)
            if (__all_sync(0xffffffffu, vmax < M[ri] - 32.0f)) continue;
            float nm = fmaxf(M[ri], vmax);
            float se = 0.f;
#pragma unroll
            for (int nf = 0; nf < 8; nf++) {
                se += ex2(acc[mf][nf][rp * 2] - nm);
                se += ex2(acc[mf][nf][rp * 2 + 1] - nm);
            }
            L[ri] = L[ri] * ex2(M[ri] - nm) + se;
            M[ri] = nm;
        }

        CP_WAIT0();
        __syncthreads();
    }

#pragma unroll
    for (int ri = 0; ri < 4; ri++) {
#pragma unroll
        for (int off = 1; off <= 2; off <<= 1) {
            float om = __shfl_xor_sync(0xffffffffu, M[ri], off);
            float ol = __shfl_xor_sync(0xffffffffu, L[ri], off);
            float nm = fmaxf(M[ri], om);
            L[ri] = L[ri] * ex2(M[ri] - nm) + ol * ex2(om - nm);
            M[ri] = nm;
        }
    }

    float* msc = (float*)(smem + OFF_A);   // [2][128]
    float* lsc = msc + 256;
    if ((lid & 3) == 0) {
#pragma unroll
        for (int ri = 0; ri < 4; ri++) {
            int row = warp_m * 32 + (ri >> 1) * 16 + (ri & 1) * 8 + (lid >> 2);
            msc[warp_n * 128 + row] = M[ri];
            lsc[warp_n * 128 + row] = L[ri];
        }
    }
    __syncthreads();
    if (tid < 128) {
        float m0 = msc[tid], m1 = msc[128 + tid];
        float nm = fmaxf(m0, m1);
        float Lm = lsc[tid] * ex2(m0 - nm) + lsc[128 + tid] * ex2(m1 - nm);
        int o = blockIdx.y * BN + row0 + tid;
        g_pmax[o] = nm;
        g_pse[o]  = Lm;
    }

    // ---- fused combine: 4th CTA to finish this row block combines it ----
    __syncthreads();
    if (tid == 0) {
        __threadfence();
        int v = atomicAdd(&g_tix[blockIdx.x], 1);
        do_combine = (v == NSPLIT - 1);
    }
    __syncthreads();
    if (!do_combine) return;
    __threadfence();   // acquire: see other CTAs' partials

    const int is64 = g_is64;
    double c = 0.0;
    if (tid < 128) {
        const int j = row0 + tid;
        float Mx = -3.0e38f;
#pragma unroll
        for (int s = 0; s < NSPLIT; s++) Mx = fmaxf(Mx, g_pmax[s * BN + j]);
        float W = 0.f;
#pragma unroll
        for (int s = 0; s < NSPLIT; s++)
            W += g_pse[s * BN + j] * ex2(g_pmax[s * BN + j] - Mx);
        double Sj = g_S[j] - (double)BN * ((double)Mx * LN2)
                  - (double)BN * (double)__logf(W + 1e-12f);
        float mc = (float)g_cnt[lab(labels, j, is64)];
        float w = mc / (mc + 1e-12f);
        c = (double)w * Sj;
    }
#pragma unroll
    for (int o = 16; o >= 1; o >>= 1)
        c += __shfl_xor_sync(0xffffffffu, c, o);
    if (lid == 0) redC[wid] = c;
    __syncthreads();
    if (tid == 0) {
        double v = redC[0] + redC[1] + redC[2] + redC[3];
        atomicAdd(&g_acc, v);
        __threadfence();
        int done = atomicAdd(&g_tix2, 1);
        if (done == (BN / 128) - 1) {
            __threadfence();
            out[0] = (float)(-g_acc / ((double)BN * (double)BN));
        }
    }
}

// ---------------------------------------------------------------------------
extern "C" void kernel_launch(void* const* d_in, const int* in_sizes, int n_in,
                              void* d_out, int out_size) {
    const float* feats = (const float*)d_in[0];
    const void*  labels = d_in[1];
    const float* cov   = (const float*)d_in[2];
    float* out = (float*)d_out;

    cudaFuncSetAttribute(k_gemm_mma,
                         cudaFuncAttributeMaxDynamicSharedMemorySize, SMEM_BYTES);
    cudaFuncSetAttribute(k_u_grouped,
                         cudaFuncAttributeMaxDynamicSharedMemorySize, U_SMEM);

    k_pre<<<9, 1024>>>(labels, feats);
    k_u_grouped<<<CN, 256, U_SMEM>>>(feats, cov);
    dim3 grid(BN / 128, NSPLIT);
    k_gemm_mma<<<grid, 256, SMEM_BYTES>>>(labels, out);
}